// round 13
// baseline (speedup 1.0000x reference)
#include <cuda_runtime.h>
#include <cuda_bf16.h>
#include <math.h>

#define Bn 64
#define Sn 512
#define Hn 1024
#define En 128
#define Ln 49
#define G3 3072            // 3*H
#define IW 1152            // E+H
#define NEGV (-1e12f)

#define NCTA 128
#define TPB  256

// k_gx_mma: 128x128 CTA tile, 2-stage cp.async, 2 CTAs/SM (at HMMA ceiling)
#define GX_SMEM (2 * 2 * 128 * 64 * 2)   // 65536

// k_scan_tc smem: w 96KB + h warp-private 8x8KB + psum 8x32x50 fp32 50KB
#define SCANTC_SMEM (98304 + 65536 + 51200)   // 215040

// ---------------- device scratch ----------------
__device__ __align__(16) float g_gx[(size_t)Bn * Sn * G3];     // [t][b][3H]
__device__ __align__(16) float g_outs[(size_t)Bn * Sn * Hn];   // [b][t][H]
__device__ __align__(16) float g_lt[Ln * G3];
__device__ __align__(16) __nv_bfloat16 g_hbf[2][Bn * Hn];      // bf16 h ping-pong
__device__ __align__(16) uint4 g_abf[(size_t)Bn * Sn * 128];   // bf16 A [m=t*64+b][1024]
__device__ __align__(16) uint4 g_bbf[(size_t)G3 * 128];        // bf16 B [g][1024]
// per-group barrier state: counters and gen word on separate 128B lines
__device__ __align__(128) unsigned g_sub2[2][32];   // [grp][0..3]=sub counters, [grp][8]=root
__device__ __align__(128) unsigned g_gen3[2][32];   // [grp][0]=generation (monotonic)

// ---------------- PTX helpers ----------------
__device__ __forceinline__ unsigned smem_u32(const void* p) {
    unsigned a;
    asm("{ .reg .u64 t; cvta.to.shared.u64 t, %1; cvt.u32.u64 %0, t; }" : "=r"(a) : "l"(p));
    return a;
}
__device__ __forceinline__ void ldsm_x4(unsigned* r, unsigned addr) {
    asm volatile("ldmatrix.sync.aligned.m8n8.x4.shared.b16 {%0,%1,%2,%3}, [%4];"
                 : "=r"(r[0]), "=r"(r[1]), "=r"(r[2]), "=r"(r[3]) : "r"(addr));
}
__device__ __forceinline__ void ldsm_x2(unsigned* r, unsigned addr) {
    asm volatile("ldmatrix.sync.aligned.m8n8.x2.shared.b16 {%0,%1}, [%2];"
                 : "=r"(r[0]), "=r"(r[1]) : "r"(addr));
}
__device__ __forceinline__ void mma_bf16(float* c, const unsigned* a, const unsigned* b) {
    asm volatile(
        "mma.sync.aligned.m16n8k16.row.col.f32.bf16.bf16.f32 "
        "{%0,%1,%2,%3}, {%4,%5,%6,%7}, {%8,%9}, {%0,%1,%2,%3};"
        : "+f"(c[0]), "+f"(c[1]), "+f"(c[2]), "+f"(c[3])
        : "r"(a[0]), "r"(a[1]), "r"(a[2]), "r"(a[3]), "r"(b[0]), "r"(b[1]));
}
__device__ __forceinline__ float tanhfast(float x) {
    float y;
    asm("tanh.approx.f32 %0, %1;" : "=f"(y) : "f"(x));
    return y;
}
__device__ __forceinline__ float sigfast(float x) {
    return __fdividef(1.f, 1.f + __expf(-x));
}
#define CP_ASYNC16(sa, gp) \
    asm volatile("cp.async.cg.shared.global [%0], [%1], 16;" :: "r"(sa), "l"(gp) : "memory")
#define CP_COMMIT() asm volatile("cp.async.commit_group;" ::: "memory")
#define CP_WAITN(n) asm volatile("cp.async.wait_group %0;" :: "n"(n) : "memory")

// ---------------- split per-group barrier (arrive / per-warp wait) -------
__device__ __forceinline__ void garrive(int grp, int idx) {
    __threadfence();
    __syncthreads();
    if (threadIdx.x == 0) {
        if (atomicAdd(&g_sub2[grp][idx >> 4], 1u) == 15u) {
            atomicExch(&g_sub2[grp][idx >> 4], 0u);
            if (atomicAdd(&g_sub2[grp][8], 1u) == 3u) {
                atomicExch(&g_sub2[grp][8], 0u);
                __threadfence();
                atomicAdd(&g_gen3[grp][0], 1u);
            }
        }
    }
}
__device__ __forceinline__ void gwait(int grp, unsigned base, unsigned target) {
    if ((threadIdx.x & 31) == 0) {
        while ((unsigned)(*((volatile unsigned*)&g_gen3[grp][0]) - base) < target) {}
    }
    __syncwarp();
    __threadfence();
}

// ---------------- IOBES ----------------
__device__ __forceinline__ bool allowf(int prev, int nxt) {
    if (prev == 0 || ((prev - 1) & 3) >= 2) {
        if (nxt == 0) return true;
        int np = (nxt - 1) & 3;
        return (np == 0) || (np == 3);
    } else {
        if (nxt == 0) return false;
        int np = (nxt - 1) & 3;
        return (((nxt - 1) >> 2) == ((prev - 1) >> 2)) && (np == 1 || np == 2);
    }
}
__device__ __forceinline__ int clamp_lab(int v) {
    return v < 0 ? 0 : (v > Ln - 1 ? Ln - 1 : v);
}

// ---------------- k_lt ----------------
__global__ void k_lt(const float* __restrict__ emb,
                     const float* __restrict__ w_ih,
                     const float* __restrict__ b_ih) {
    int l = blockIdx.y;
    int g = blockIdx.x * 128 + threadIdx.x;
    __shared__ float es[En];
    if (threadIdx.x < En) es[threadIdx.x] = emb[l * En + threadIdx.x];
    __syncthreads();
    float acc = b_ih[g];
    const float* w = w_ih + (size_t)g * IW;
#pragma unroll 8
    for (int e = 0; e < En; e++) acc = fmaf(es[e], w[e], acc);
    g_lt[l * G3 + g] = acc;
}

// ---------------- bf16 cast kernels ----------------
__device__ __forceinline__ unsigned pk2(float a, float b) {
    __nv_bfloat162 h = __floats2bfloat162_rn(a, b);
    return *(unsigned*)&h;
}
__global__ void k_cast_a(const float* __restrict__ we) {
    size_t c = (size_t)blockIdx.x * 256 + threadIdx.x;
    int m = (int)(c >> 7), kq = (int)(c & 127);
    int t = m >> 6, b = m & 63;
    const float4* src = (const float4*)(we + ((size_t)b * Sn + t) * Hn + kq * 8);
    float4 f0 = src[0], f1 = src[1];
    uint4 o;
    o.x = pk2(f0.x, f0.y); o.y = pk2(f0.z, f0.w);
    o.z = pk2(f1.x, f1.y); o.w = pk2(f1.z, f1.w);
    g_abf[c] = o;
}
__global__ void k_cast_b(const float* __restrict__ w_ih) {
    size_t c = (size_t)blockIdx.x * 256 + threadIdx.x;
    int g = (int)(c >> 7), kq = (int)(c & 127);
    const float4* src = (const float4*)(w_ih + (size_t)g * IW + En + kq * 8);
    float4 f0 = src[0], f1 = src[1];
    uint4 o;
    o.x = pk2(f0.x, f0.y); o.y = pk2(f0.z, f0.w);
    o.z = pk2(f1.x, f1.y); o.w = pk2(f1.z, f1.w);
    g_bbf[c] = o;
}

// ---------------- k_gx_mma: HMMA bf16 GEMM, 2-stage cp.async (ceiling) ----
__global__ void __launch_bounds__(256, 2) k_gx_mma(const int* __restrict__ lab) {
    extern __shared__ char smem[];
    unsigned sb = smem_u32(smem);
    const unsigned aOff[2] = { 0u, 32768u };
    const unsigned bOff[2] = { 16384u, 49152u };

    int tid = threadIdx.x, lane = tid & 31, wid = tid >> 5;
    int wm = wid >> 2, wn = wid & 3;
    int n0 = blockIdx.x * 128;
    int m0 = blockIdx.y * 128;

    float acc[16][4];
#pragma unroll
    for (int i = 0; i < 16; i++)
#pragma unroll
        for (int j = 0; j < 4; j++) acc[i][j] = 0.f;

#pragma unroll
    for (int q = 0; q < 4; q++) {
        int idx = tid * 4 + q, r = idx >> 3, i = idx & 7;
        unsigned off = (unsigned)(r * 128 + ((i ^ (r & 7)) << 4));
        CP_ASYNC16(sb + aOff[0] + off, g_abf + (size_t)(m0 + r) * 128 + i);
        CP_ASYNC16(sb + bOff[0] + off, g_bbf + (size_t)(n0 + r) * 128 + i);
    }
    CP_COMMIT();

    int il = lane & 15;
    for (int kc = 0; kc < 16; kc++) {
        int s = kc & 1;
        if (kc < 15) {
            int kn = kc + 1, sn = kn & 1;
#pragma unroll
            for (int q = 0; q < 4; q++) {
                int idx = tid * 4 + q, r = idx >> 3, i = idx & 7;
                unsigned off = (unsigned)(r * 128 + ((i ^ (r & 7)) << 4));
                CP_ASYNC16(sb + aOff[sn] + off, g_abf + (size_t)(m0 + r) * 128 + kn * 8 + i);
                CP_ASYNC16(sb + bOff[sn] + off, g_bbf + (size_t)(n0 + r) * 128 + kn * 8 + i);
            }
            CP_COMMIT();
            CP_WAITN(1);
        } else {
            CP_WAITN(0);
        }
        __syncthreads();
#pragma unroll
        for (int ks = 0; ks < 4; ks++) {
            unsigned afr[4][4], bfr[4][2];
#pragma unroll
            for (int mt = 0; mt < 4; mt++) {
                int row = wm * 64 + mt * 16 + il;
                int ch = ks * 2 + (lane >> 4);
                ldsm_x4(afr[mt], sb + aOff[s] + row * 128 + ((ch ^ (row & 7)) << 4));
            }
#pragma unroll
            for (int nt = 0; nt < 4; nt++) {
                int row = wn * 32 + nt * 8 + (il & 7);
                int ch = ks * 2 + (il >> 3);
                ldsm_x2(bfr[nt], sb + bOff[s] + row * 128 + ((ch ^ (row & 7)) << 4));
            }
#pragma unroll
            for (int mt = 0; mt < 4; mt++)
#pragma unroll
                for (int nt = 0; nt < 4; nt++)
                    mma_bf16(acc[mt * 4 + nt], afr[mt], bfr[nt]);
        }
        __syncthreads();
    }

    int r_in = lane >> 2, c2 = (lane & 3) * 2;
#pragma unroll
    for (int mt = 0; mt < 4; mt++) {
        int r0 = m0 + wm * 64 + mt * 16 + r_in;
        int r1 = r0 + 8;
        int t0 = r0 >> 6, bb0 = r0 & 63;
        int t1 = r1 >> 6, bb1 = r1 & 63;
        int p0 = (t0 == 0) ? 0 : clamp_lab(lab[bb0 * Sn + t0 - 1]);
        int p1 = (t1 == 0) ? 0 : clamp_lab(lab[bb1 * Sn + t1 - 1]);
        const float* lt0 = g_lt + (size_t)p0 * G3;
        const float* lt1 = g_lt + (size_t)p1 * G3;
        float* o0 = g_gx + (size_t)r0 * G3;
        float* o1 = g_gx + (size_t)r1 * G3;
#pragma unroll
        for (int nt = 0; nt < 4; nt++) {
            int n = n0 + wn * 32 + nt * 8 + c2;
            float* a = acc[mt * 4 + nt];
            float2 v0, v1;
            v0.x = a[0] + lt0[n]; v0.y = a[1] + lt0[n + 1];
            v1.x = a[2] + lt1[n]; v1.y = a[3] + lt1[n + 1];
            *(float2*)(o0 + n) = v0;
            *(float2*)(o1 + n) = v1;
        }
    }
}

// ---------------- k_scan_tc: batch-split persistent GRU scan --------------
// 2 independent groups of 64 CTAs. Group g owns batches [g*32, g*32+32).
// CTA idx owns 16 h-cols at c0=idx*16 -> 48 W rows. Warp w owns k16 slot w.
// WARP-PRIVATE h staging: warp w stages only its k-slot columns (8KB) via
// per-warp cp.async; waits are warp-local (wait_group+syncwarp). NO block
// syncs inside the MMA phase. B fragments via ldsm_x4 (2 n-tiles per load).
#define PSR 50      // psum row stride (floats)
__global__ void __launch_bounds__(TPB, 1) k_scan_tc(const float* __restrict__ w_hh,
                                                    const float* __restrict__ b_hh) {
    extern __shared__ char smem[];
    unsigned sb = smem_u32(smem);
    char* w_sm = smem;                        // bf16 [8 kc][48 j][256B], swizzled
    float* psum = (float*)(smem + 98304 + 65536);  // [8 w][32][PSR]
    __shared__ float bhh_s[48];
    __shared__ unsigned s_base;
    const unsigned swb = sb;
    const unsigned sh0 = sb + 98304;          // h: [8 warps][8 kc][2 half][32 row][16B]

    int cta = blockIdx.x, tid = threadIdx.x;
    int lane = tid & 31, wid = tid >> 5;
    int grp = cta >> 6, idx = cta & 63;
    int c0 = idx * 16;
    int b0 = grp * 32;

    if (tid == 0) s_base = *((volatile unsigned*)&g_gen3[grp][0]);

    // one-time: weights (48 rows x 1024) -> bf16 smem (ldmatrix layout)
    for (int cid = tid; cid < 6144; cid += TPB) {
        int j = cid >> 7, kchunk = cid & 127;
        int kc = kchunk >> 4, c16 = kchunk & 15;
        int wrow = (j >> 4) * Hn + c0 + (j & 15);
        const float4* s = (const float4*)(w_hh + (size_t)wrow * Hn + kchunk * 8);
        float4 f0 = s[0], f1 = s[1];
        uint4 o;
        o.x = pk2(f0.x, f0.y); o.y = pk2(f0.z, f0.w);
        o.z = pk2(f1.x, f1.y); o.w = pk2(f1.z, f1.w);
        *(uint4*)(w_sm + kc * 12288 + j * 256 + ((c16 ^ (j & 7)) << 4)) = o;
    }
    if (tid < 48) bhh_s[tid] = b_hh[(tid >> 4) * Hn + c0 + (tid & 15)];

    // zero this group's h rows in buffer 0
    for (int i2 = idx * TPB + tid; i2 < 32 * Hn * 2 / 16; i2 += 64 * TPB)
        ((uint4*)(g_hbf[0] + (size_t)b0 * Hn))[i2] = make_uint4(0u, 0u, 0u, 0u);

    garrive(grp, idx);
    unsigned base = s_base;
    unsigned bt = 1;
    gwait(grp, base, bt);

    int il = lane & 15;
    int r_in = lane >> 2, cc2 = (lane & 3) * 2;
    int kk = wid;                        // this warp's k16 slot (0..7)
    unsigned whb = sh0 + (unsigned)kk * 8192;   // warp-private h region

    // epilogue task mapping: 32 batches x 16 cols = 512 tasks, 2/thread
    int ti[2], tc[2];
    ti[0] = tid >> 4;           tc[0] = tid & 15;
    ti[1] = (tid + TPB) >> 4;   tc[1] = tid & 15;
    float hprev[2] = { 0.f, 0.f };

    // prefetch gx for t=0
    float gxa[2][3];
#pragma unroll
    for (int q = 0; q < 2; q++) {
        const float* gxr = g_gx + (size_t)(b0 + ti[q]) * G3 + c0 + tc[q];
        gxa[q][0] = __ldg(gxr);
        gxa[q][1] = __ldg(gxr + 1024);
        gxa[q][2] = __ldg(gxr + 2048);
    }

    for (int t = 0; t < Sn; t++) {
        const __nv_bfloat16* hb = g_hbf[t & 1] + (size_t)b0 * Hn;

        // warp-private staging: lane stages row=lane for all (kc, half)
        // of this warp's k-slot. Layout [kc][half][row]: conflict-free ldsm.
        {
            const __nv_bfloat16* src = hb + (size_t)lane * Hn + kk * 16;
#pragma unroll
            for (int u = 0; u < 16; u++) {
                int kc = u >> 1, half = u & 1;
                unsigned dst = whb + (unsigned)(kc * 1024 + half * 512 + lane * 16);
                CP_ASYNC16(dst, src + kc * 128 + half * 8);
                if (u == 7) CP_COMMIT();
            }
            CP_COMMIT();
        }

        float acc[12][4];
#pragma unroll
        for (int i = 0; i < 12; i++)
#pragma unroll
            for (int j = 0; j < 4; j++) acc[i][j] = 0.f;

#pragma unroll
        for (int kc = 0; kc < 8; kc++) {
            if (kc == 0) { CP_WAITN(1); __syncwarp(); }
            if (kc == 4) { CP_WAITN(0); __syncwarp(); }
            unsigned a[2][4];
#pragma unroll
            for (int mt = 0; mt < 2; mt++) {
                int row = mt * 16 + il;
                ldsm_x4(a[mt], whb + (unsigned)(kc * 1024 + (lane >> 4) * 512 + row * 16));
            }
            unsigned b4[3][4];
#pragma unroll
            for (int j = 0; j < 3; j++) {
                int row = (2 * j + (lane >> 4)) * 8 + (lane & 7);
                int ch = kk * 2 + ((lane >> 3) & 1);
                ldsm_x4(b4[j], swb + kc * 12288 + row * 256 + ((ch ^ (row & 7)) << 4));
            }
#pragma unroll
            for (int mt = 0; mt < 2; mt++)
#pragma unroll
                for (int j = 0; j < 3; j++) {
                    mma_bf16(acc[mt * 6 + 2 * j],     a[mt], &b4[j][0]);
                    mma_bf16(acc[mt * 6 + 2 * j + 1], a[mt], &b4[j][2]);
                }
        }

        // write this warp's 32x48 partial
        float* ps = psum + wid * (32 * PSR);
#pragma unroll
        for (int mt = 0; mt < 2; mt++) {
            int mr = mt * 16 + r_in;
#pragma unroll
            for (int nt = 0; nt < 6; nt++) {
                int n = nt * 8 + cc2;
                float* a = acc[mt * 6 + nt];
                *(float2*)(ps + mr * PSR + n)       = make_float2(a[0], a[1]);
                *(float2*)(ps + (mr + 8) * PSR + n) = make_float2(a[2], a[3]);
            }
        }
        __syncthreads();

        // epilogue: compute h(t+1), publish bf16 h first (cross-CTA data)
        __nv_bfloat16* hbn = g_hbf[(t + 1) & 1] + (size_t)b0 * Hn;
        float hnew2[2];
#pragma unroll
        for (int q = 0; q < 2; q++) {
            int i = ti[q], c = tc[q];
            float ghr = bhh_s[c], ghz = bhh_s[16 + c], ghn = bhh_s[32 + c];
#pragma unroll
            for (int w = 0; w < 8; w++) {
                const float* ps2 = psum + w * (32 * PSR) + i * PSR;
                ghr += ps2[c];
                ghz += ps2[16 + c];
                ghn += ps2[32 + c];
            }
            float r = sigfast(gxa[q][0] + ghr);
            float z = sigfast(gxa[q][1] + ghz);
            float n = tanhfast(gxa[q][2] + r * ghn);
            float hnew = (1.f - z) * n + z * hprev[q];
            hprev[q] = hnew;
            hnew2[q] = hnew;
            hbn[i * Hn + c0 + c] = __float2bfloat16(hnew);
        }

        if (t + 1 < Sn) {
            garrive(grp, idx);
#pragma unroll
            for (int q = 0; q < 2; q++)
                g_outs[(size_t)(b0 + ti[q]) * (Sn * Hn) + (size_t)t * Hn + c0 + tc[q]] = hnew2[q];
            const float* gxt = g_gx + (size_t)(t + 1) * (Bn * G3);
#pragma unroll
            for (int q = 0; q < 2; q++) {
                const float* gxr = gxt + (size_t)(b0 + ti[q]) * G3 + c0 + tc[q];
                gxa[q][0] = __ldg(gxr);
                gxa[q][1] = __ldg(gxr + 1024);
                gxa[q][2] = __ldg(gxr + 2048);
            }
            bt++;
            gwait(grp, base, bt);
        } else {
#pragma unroll
            for (int q = 0; q < 2; q++)
                g_outs[(size_t)(b0 + ti[q]) * (Sn * Hn) + (size_t)t * Hn + c0 + tc[q]] = hnew2[q];
        }
    }
}

// ---------------- k_logits ----------------
__global__ void __launch_bounds__(256) k_logits(const int* __restrict__ lab,
                                                const float* __restrict__ w_out,
                                                const float* __restrict__ b_out,
                                                float* __restrict__ out) {
    __shared__ float a_sm[16][68];
    __shared__ float b_sm[16][64];
    int m0 = blockIdx.x * 64;
    int tid = threadIdx.x;

    int ar = tid >> 2, akq = tid & 3;
    int bl = tid & 63, bkq = tid >> 6;
    const float* aptr = g_outs + (size_t)(m0 + ar) * Hn + akq * 4;
    int ty = tid >> 4, tx = tid & 15;

    float acc[4][4];
#pragma unroll
    for (int q = 0; q < 4; q++)
#pragma unroll
        for (int p = 0; p < 4; p++) acc[q][p] = 0.f;

    float4 av = *(const float4*)(aptr);
    float4 bv = make_float4(0.f, 0.f, 0.f, 0.f);
    if (bl < Ln) bv = *(const float4*)(w_out + (size_t)bl * Hn + bkq * 4);

    for (int k0 = 0; k0 < Hn; k0 += 16) {
        a_sm[akq * 4 + 0][ar] = av.x;
        a_sm[akq * 4 + 1][ar] = av.y;
        a_sm[akq * 4 + 2][ar] = av.z;
        a_sm[akq * 4 + 3][ar] = av.w;
        b_sm[bkq * 4 + 0][bl] = bv.x;
        b_sm[bkq * 4 + 1][bl] = bv.y;
        b_sm[bkq * 4 + 2][bl] = bv.z;
        b_sm[bkq * 4 + 3][bl] = bv.w;
        __syncthreads();
        if (k0 + 16 < Hn) {
            av = *(const float4*)(aptr + k0 + 16);
            if (bl < Ln) bv = *(const float4*)(w_out + (size_t)bl * Hn + bkq * 4 + k0 + 16);
        }
#pragma unroll
        for (int kk = 0; kk < 16; kk++) {
            float4 a4 = *(const float4*)&a_sm[kk][ty * 4];
            float4 b4 = *(const float4*)&b_sm[kk][tx * 4];
#pragma unroll
            for (int q = 0; q < 4; q++) {
                float aval = (q == 0) ? a4.x : (q == 1) ? a4.y : (q == 2) ? a4.z : a4.w;
                acc[q][0] = fmaf(aval, b4.x, acc[q][0]);
                acc[q][1] = fmaf(aval, b4.y, acc[q][1]);
                acc[q][2] = fmaf(aval, b4.z, acc[q][2]);
                acc[q][3] = fmaf(aval, b4.w, acc[q][3]);
            }
        }
        __syncthreads();
    }

#pragma unroll
    for (int q = 0; q < 4; q++) {
        int row = m0 + ty * 4 + q;
        int b = row >> 9, t = row & 511;
        int prev = (t == 0) ? 0 : clamp_lab(lab[b * Sn + t - 1]);
#pragma unroll
        for (int p = 0; p < 4; p++) {
            int l = tx * 4 + p;
            if (l < Ln) {
                float v = allowf(prev, l) ? (acc[q][p] + b_out[l]) : NEGV;
                out[(size_t)row * Ln + l] = v;
            }
        }
    }
}

// ---------------- launcher ----------------
extern "C" void kernel_launch(void* const* d_in, const int* in_sizes, int n_in,
                              void* d_out, int out_size) {
    const float* we    = nullptr;
    const int*   lab   = nullptr;
    const float* emb   = nullptr;
    const float* w_ih  = nullptr;
    const float* w_hh  = nullptr;
    const float* b_ih  = nullptr;
    const float* b_hh  = nullptr;
    const float* w_out = nullptr;
    const float* b_out = nullptr;

    for (int i = 0; i < n_in; i++) {
        int n = in_sizes[i];
        const void* p = d_in[i];
        switch (n) {
            case 33554432: we    = (const float*)p; break;
            case 32768:    lab   = (const int*)p;   break;
            case 6272:     emb   = (const float*)p; break;
            case 3538944:  w_ih  = (const float*)p; break;
            case 3145728:  w_hh  = (const float*)p; break;
            case 50176:    w_out = (const float*)p; break;
            case 49:       b_out = (const float*)p; break;
            case 3072:
                if (!b_ih) b_ih = (const float*)p; else b_hh = (const float*)p;
                break;
            default: break;
        }
    }
    float* out = (float*)d_out;

    cudaFuncSetAttribute(k_gx_mma,  cudaFuncAttributeMaxDynamicSharedMemorySize, GX_SMEM);
    cudaFuncSetAttribute(k_scan_tc, cudaFuncAttributeMaxDynamicSharedMemorySize, SCANTC_SMEM);

    k_lt      <<<dim3(24, Ln), 128>>>(emb, w_ih, b_ih);
    k_cast_a  <<<16384, 256>>>(we);
    k_cast_b  <<<1536, 256>>>(w_ih);
    k_gx_mma  <<<dim3(24, 256), 256, GX_SMEM>>>(lab);
    k_scan_tc <<<NCTA, TPB, SCANTC_SMEM>>>(w_hh, b_hh);
    k_logits  <<<Bn * Sn / 64, 256>>>(lab, w_out, b_out, out);
}

// round 14
// speedup vs baseline: 1.3819x; 1.3819x over previous
#include <cuda_runtime.h>
#include <cuda_bf16.h>
#include <math.h>

#define Bn 64
#define Sn 512
#define Hn 1024
#define En 128
#define Ln 49
#define G3 3072            // 3*H
#define IW 1152            // E+H
#define NEGV (-1e12f)

#define NCTA 128
#define TPB  256

// k_gx_mma: 128x128 CTA tile, 2-stage cp.async, 2 CTAs/SM (at HMMA ceiling)
#define GX_SMEM (2 * 2 * 128 * 64 * 2)   // 65536

// k_scan_tc smem: w 96KB + h 4-pair 64KB + psum 8x32x50 fp32 50KB
#define SCANTC_SMEM (98304 + 65536 + 51200)   // 215040

// ---------------- device scratch ----------------
__device__ __align__(16) float g_gx[(size_t)Bn * Sn * G3];     // [t][b][3H]
__device__ __align__(16) float g_outs[(size_t)Bn * Sn * Hn];   // [b][t][H]
__device__ __align__(16) float g_lt[Ln * G3];
__device__ __align__(16) __nv_bfloat16 g_hbf[2][Bn * Hn];      // bf16 h ping-pong
__device__ __align__(16) uint4 g_abf[(size_t)Bn * Sn * 128];   // bf16 A [m=t*64+b][1024]
__device__ __align__(16) uint4 g_bbf[(size_t)G3 * 128];        // bf16 B [g][1024]
// per-group barrier state: counters and gen word on separate 128B lines
__device__ __align__(128) unsigned g_sub2[2][32];   // [grp][0..3]=sub counters, [grp][8]=root
__device__ __align__(128) unsigned g_gen3[2][32];   // [grp][0]=generation (monotonic)

// ---------------- PTX helpers ----------------
__device__ __forceinline__ unsigned smem_u32(const void* p) {
    unsigned a;
    asm("{ .reg .u64 t; cvta.to.shared.u64 t, %1; cvt.u32.u64 %0, t; }" : "=r"(a) : "l"(p));
    return a;
}
__device__ __forceinline__ void ldsm_x4(unsigned* r, unsigned addr) {
    asm volatile("ldmatrix.sync.aligned.m8n8.x4.shared.b16 {%0,%1,%2,%3}, [%4];"
                 : "=r"(r[0]), "=r"(r[1]), "=r"(r[2]), "=r"(r[3]) : "r"(addr));
}
__device__ __forceinline__ void ldsm_x2(unsigned* r, unsigned addr) {
    asm volatile("ldmatrix.sync.aligned.m8n8.x2.shared.b16 {%0,%1}, [%2];"
                 : "=r"(r[0]), "=r"(r[1]) : "r"(addr));
}
__device__ __forceinline__ void mma_bf16(float* c, const unsigned* a, const unsigned* b) {
    asm volatile(
        "mma.sync.aligned.m16n8k16.row.col.f32.bf16.bf16.f32 "
        "{%0,%1,%2,%3}, {%4,%5,%6,%7}, {%8,%9}, {%0,%1,%2,%3};"
        : "+f"(c[0]), "+f"(c[1]), "+f"(c[2]), "+f"(c[3])
        : "r"(a[0]), "r"(a[1]), "r"(a[2]), "r"(a[3]), "r"(b[0]), "r"(b[1]));
}
__device__ __forceinline__ float tanhfast(float x) {
    float y;
    asm("tanh.approx.f32 %0, %1;" : "=f"(y) : "f"(x));
    return y;
}
__device__ __forceinline__ float sigfast(float x) {
    return __fdividef(1.f, 1.f + __expf(-x));
}
#define CP_ASYNC16(sa, gp) \
    asm volatile("cp.async.cg.shared.global [%0], [%1], 16;" :: "r"(sa), "l"(gp) : "memory")
#define CP_COMMIT() asm volatile("cp.async.commit_group;" ::: "memory")
#define CP_WAITN(n) asm volatile("cp.async.wait_group %0;" :: "n"(n) : "memory")

// ---------------- split per-group barrier (arrive / per-warp wait) -------
__device__ __forceinline__ void garrive(int grp, int idx) {
    __threadfence();
    __syncthreads();
    if (threadIdx.x == 0) {
        if (atomicAdd(&g_sub2[grp][idx >> 4], 1u) == 15u) {
            atomicExch(&g_sub2[grp][idx >> 4], 0u);
            if (atomicAdd(&g_sub2[grp][8], 1u) == 3u) {
                atomicExch(&g_sub2[grp][8], 0u);
                __threadfence();
                atomicAdd(&g_gen3[grp][0], 1u);
            }
        }
    }
}
__device__ __forceinline__ void gwait(int grp, unsigned base, unsigned target) {
    if ((threadIdx.x & 31) == 0) {
        while ((unsigned)(*((volatile unsigned*)&g_gen3[grp][0]) - base) < target) {}
    }
    __syncwarp();
    __threadfence();
}

// ---------------- IOBES ----------------
__device__ __forceinline__ bool allowf(int prev, int nxt) {
    if (prev == 0 || ((prev - 1) & 3) >= 2) {
        if (nxt == 0) return true;
        int np = (nxt - 1) & 3;
        return (np == 0) || (np == 3);
    } else {
        if (nxt == 0) return false;
        int np = (nxt - 1) & 3;
        return (((nxt - 1) >> 2) == ((prev - 1) >> 2)) && (np == 1 || np == 2);
    }
}
__device__ __forceinline__ int clamp_lab(int v) {
    return v < 0 ? 0 : (v > Ln - 1 ? Ln - 1 : v);
}

// ---------------- k_lt ----------------
__global__ void k_lt(const float* __restrict__ emb,
                     const float* __restrict__ w_ih,
                     const float* __restrict__ b_ih) {
    int l = blockIdx.y;
    int g = blockIdx.x * 128 + threadIdx.x;
    __shared__ float es[En];
    if (threadIdx.x < En) es[threadIdx.x] = emb[l * En + threadIdx.x];
    __syncthreads();
    float acc = b_ih[g];
    const float* w = w_ih + (size_t)g * IW;
#pragma unroll 8
    for (int e = 0; e < En; e++) acc = fmaf(es[e], w[e], acc);
    g_lt[l * G3 + g] = acc;
}

// ---------------- bf16 cast kernels ----------------
__device__ __forceinline__ unsigned pk2(float a, float b) {
    __nv_bfloat162 h = __floats2bfloat162_rn(a, b);
    return *(unsigned*)&h;
}
__global__ void k_cast_a(const float* __restrict__ we) {
    size_t c = (size_t)blockIdx.x * 256 + threadIdx.x;
    int m = (int)(c >> 7), kq = (int)(c & 127);
    int t = m >> 6, b = m & 63;
    const float4* src = (const float4*)(we + ((size_t)b * Sn + t) * Hn + kq * 8);
    float4 f0 = src[0], f1 = src[1];
    uint4 o;
    o.x = pk2(f0.x, f0.y); o.y = pk2(f0.z, f0.w);
    o.z = pk2(f1.x, f1.y); o.w = pk2(f1.z, f1.w);
    g_abf[c] = o;
}
__global__ void k_cast_b(const float* __restrict__ w_ih) {
    size_t c = (size_t)blockIdx.x * 256 + threadIdx.x;
    int g = (int)(c >> 7), kq = (int)(c & 127);
    const float4* src = (const float4*)(w_ih + (size_t)g * IW + En + kq * 8);
    float4 f0 = src[0], f1 = src[1];
    uint4 o;
    o.x = pk2(f0.x, f0.y); o.y = pk2(f0.z, f0.w);
    o.z = pk2(f1.x, f1.y); o.w = pk2(f1.z, f1.w);
    g_bbf[c] = o;
}

// ---------------- k_gx_mma: HMMA bf16 GEMM, 2-stage cp.async (ceiling) ----
__global__ void __launch_bounds__(256, 2) k_gx_mma(const int* __restrict__ lab) {
    extern __shared__ char smem[];
    unsigned sb = smem_u32(smem);
    const unsigned aOff[2] = { 0u, 32768u };
    const unsigned bOff[2] = { 16384u, 49152u };

    int tid = threadIdx.x, lane = tid & 31, wid = tid >> 5;
    int wm = wid >> 2, wn = wid & 3;
    int n0 = blockIdx.x * 128;
    int m0 = blockIdx.y * 128;

    float acc[16][4];
#pragma unroll
    for (int i = 0; i < 16; i++)
#pragma unroll
        for (int j = 0; j < 4; j++) acc[i][j] = 0.f;

#pragma unroll
    for (int q = 0; q < 4; q++) {
        int idx = tid * 4 + q, r = idx >> 3, i = idx & 7;
        unsigned off = (unsigned)(r * 128 + ((i ^ (r & 7)) << 4));
        CP_ASYNC16(sb + aOff[0] + off, g_abf + (size_t)(m0 + r) * 128 + i);
        CP_ASYNC16(sb + bOff[0] + off, g_bbf + (size_t)(n0 + r) * 128 + i);
    }
    CP_COMMIT();

    int il = lane & 15;
    for (int kc = 0; kc < 16; kc++) {
        int s = kc & 1;
        if (kc < 15) {
            int kn = kc + 1, sn = kn & 1;
#pragma unroll
            for (int q = 0; q < 4; q++) {
                int idx = tid * 4 + q, r = idx >> 3, i = idx & 7;
                unsigned off = (unsigned)(r * 128 + ((i ^ (r & 7)) << 4));
                CP_ASYNC16(sb + aOff[sn] + off, g_abf + (size_t)(m0 + r) * 128 + kn * 8 + i);
                CP_ASYNC16(sb + bOff[sn] + off, g_bbf + (size_t)(n0 + r) * 128 + kn * 8 + i);
            }
            CP_COMMIT();
            CP_WAITN(1);
        } else {
            CP_WAITN(0);
        }
        __syncthreads();
#pragma unroll
        for (int ks = 0; ks < 4; ks++) {
            unsigned afr[4][4], bfr[4][2];
#pragma unroll
            for (int mt = 0; mt < 4; mt++) {
                int row = wm * 64 + mt * 16 + il;
                int ch = ks * 2 + (lane >> 4);
                ldsm_x4(afr[mt], sb + aOff[s] + row * 128 + ((ch ^ (row & 7)) << 4));
            }
#pragma unroll
            for (int nt = 0; nt < 4; nt++) {
                int row = wn * 32 + nt * 8 + (il & 7);
                int ch = ks * 2 + (il >> 3);
                ldsm_x2(bfr[nt], sb + bOff[s] + row * 128 + ((ch ^ (row & 7)) << 4));
            }
#pragma unroll
            for (int mt = 0; mt < 4; mt++)
#pragma unroll
                for (int nt = 0; nt < 4; nt++)
                    mma_bf16(acc[mt * 4 + nt], afr[mt], bfr[nt]);
        }
        __syncthreads();
    }

    int r_in = lane >> 2, c2 = (lane & 3) * 2;
#pragma unroll
    for (int mt = 0; mt < 4; mt++) {
        int r0 = m0 + wm * 64 + mt * 16 + r_in;
        int r1 = r0 + 8;
        int t0 = r0 >> 6, bb0 = r0 & 63;
        int t1 = r1 >> 6, bb1 = r1 & 63;
        int p0 = (t0 == 0) ? 0 : clamp_lab(lab[bb0 * Sn + t0 - 1]);
        int p1 = (t1 == 0) ? 0 : clamp_lab(lab[bb1 * Sn + t1 - 1]);
        const float* lt0 = g_lt + (size_t)p0 * G3;
        const float* lt1 = g_lt + (size_t)p1 * G3;
        float* o0 = g_gx + (size_t)r0 * G3;
        float* o1 = g_gx + (size_t)r1 * G3;
#pragma unroll
        for (int nt = 0; nt < 4; nt++) {
            int n = n0 + wn * 32 + nt * 8 + c2;
            float* a = acc[mt * 4 + nt];
            float2 v0, v1;
            v0.x = a[0] + lt0[n]; v0.y = a[1] + lt0[n + 1];
            v1.x = a[2] + lt1[n]; v1.y = a[3] + lt1[n + 1];
            *(float2*)(o0 + n) = v0;
            *(float2*)(o1 + n) = v1;
        }
    }
}

// ---------------- k_scan_tc: batch-split persistent GRU scan --------------
// R12 configuration (block-coalesced cp.async staging, 4 commit groups) with
// ONE change: B fragments via ldsm_x4 (2 n-tiles per load, 40 LDSM/warp/step).
#define PSR 50      // psum row stride (floats)
__global__ void __launch_bounds__(TPB, 1) k_scan_tc(const float* __restrict__ w_hh,
                                                    const float* __restrict__ b_hh) {
    extern __shared__ char smem[];
    unsigned sb = smem_u32(smem);
    char* w_sm = smem;                        // bf16 [8 kc][48 j][256B], swizzled
    float* psum = (float*)(smem + 98304 + 65536);  // [8 w][32][PSR]
    __shared__ float bhh_s[48];
    __shared__ unsigned s_base;
    const unsigned swb = sb;
    const unsigned sh0 = sb + 98304;          // h: [8 kc][32 r][256B], swizzled

    int cta = blockIdx.x, tid = threadIdx.x;
    int lane = tid & 31, wid = tid >> 5;
    int grp = cta >> 6, idx = cta & 63;
    int c0 = idx * 16;
    int b0 = grp * 32;

    if (tid == 0) s_base = *((volatile unsigned*)&g_gen3[grp][0]);

    // one-time: weights (48 rows x 1024) -> bf16 smem (ldmatrix layout)
    for (int cid = tid; cid < 6144; cid += TPB) {
        int j = cid >> 7, kchunk = cid & 127;
        int kc = kchunk >> 4, c16 = kchunk & 15;
        int wrow = (j >> 4) * Hn + c0 + (j & 15);
        const float4* s = (const float4*)(w_hh + (size_t)wrow * Hn + kchunk * 8);
        float4 f0 = s[0], f1 = s[1];
        uint4 o;
        o.x = pk2(f0.x, f0.y); o.y = pk2(f0.z, f0.w);
        o.z = pk2(f1.x, f1.y); o.w = pk2(f1.z, f1.w);
        *(uint4*)(w_sm + kc * 12288 + j * 256 + ((c16 ^ (j & 7)) << 4)) = o;
    }
    if (tid < 48) bhh_s[tid] = b_hh[(tid >> 4) * Hn + c0 + (tid & 15)];

    // zero this group's h rows in buffer 0
    for (int i2 = idx * TPB + tid; i2 < 32 * Hn * 2 / 16; i2 += 64 * TPB)
        ((uint4*)(g_hbf[0] + (size_t)b0 * Hn))[i2] = make_uint4(0u, 0u, 0u, 0u);

    garrive(grp, idx);
    unsigned base = s_base;
    unsigned bt = 1;
    gwait(grp, base, bt);

    int il = lane & 15;
    int r_in = lane >> 2, cc2 = (lane & 3) * 2;
    int kk = wid;                       // this warp's k16 slot (0..7)

    // epilogue task mapping: 32 batches x 16 cols = 512 tasks, 2/thread
    int ti[2], tc[2];
    ti[0] = tid >> 4;           tc[0] = tid & 15;
    ti[1] = (tid + TPB) >> 4;   tc[1] = tid & 15;
    float hprev[2] = { 0.f, 0.f };

    // prefetch gx for t=0
    float gxa[2][3];
#pragma unroll
    for (int q = 0; q < 2; q++) {
        const float* gxr = g_gx + (size_t)(b0 + ti[q]) * G3 + c0 + tc[q];
        gxa[q][0] = __ldg(gxr);
        gxa[q][1] = __ldg(gxr + 1024);
        gxa[q][2] = __ldg(gxr + 2048);
    }

    for (int t = 0; t < Sn; t++) {
        const __nv_bfloat16* hb = g_hbf[t & 1] + (size_t)b0 * Hn;

        // issue ALL 4 chunk-pairs of h(t) as separate commit groups (coalesced)
#pragma unroll
        for (int kcp = 0; kcp < 4; kcp++) {
#pragma unroll
            for (int q = 0; q < 4; q++) {
                int i2 = q * 256 + tid;          // 0..1023 within pair
                int r = i2 >> 5, u = i2 & 31;
                int kc = kcp * 2 + (u >> 4), c16 = u & 15;
                unsigned dst = sh0 + kc * 8192 + r * 256 + ((c16 ^ (r & 7)) << 4);
                CP_ASYNC16(dst, hb + (size_t)r * Hn + kc * 128 + c16 * 8);
            }
            CP_COMMIT();
        }

        float acc[12][4];
#pragma unroll
        for (int i = 0; i < 12; i++)
#pragma unroll
            for (int j = 0; j < 4; j++) acc[i][j] = 0.f;

#pragma unroll
        for (int kcp = 0; kcp < 4; kcp++) {
            if (kcp == 0)      CP_WAITN(3);
            else if (kcp == 1) CP_WAITN(2);
            else if (kcp == 2) CP_WAITN(1);
            else               CP_WAITN(0);
            __syncthreads();
#pragma unroll
            for (int sub = 0; sub < 2; sub++) {
                int kc = kcp * 2 + sub;
                unsigned a[2][4];
#pragma unroll
                for (int mt = 0; mt < 2; mt++) {
                    int row = mt * 16 + il;
                    int ch = kk * 2 + (lane >> 4);
                    ldsm_x4(a[mt], sh0 + kc * 8192 + row * 256 + ((ch ^ (row & 7)) << 4));
                }
                // B fragments: 3 x ldsm_x4, each covering 2 n-tiles
                unsigned b4[3][4];
#pragma unroll
                for (int j = 0; j < 3; j++) {
                    int row = (2 * j + (lane >> 4)) * 8 + (lane & 7);
                    int ch = kk * 2 + ((lane >> 3) & 1);
                    ldsm_x4(b4[j], swb + kc * 12288 + row * 256 + ((ch ^ (row & 7)) << 4));
                }
#pragma unroll
                for (int mt = 0; mt < 2; mt++)
#pragma unroll
                    for (int j = 0; j < 3; j++) {
                        mma_bf16(acc[mt * 6 + 2 * j],     a[mt], &b4[j][0]);
                        mma_bf16(acc[mt * 6 + 2 * j + 1], a[mt], &b4[j][2]);
                    }
            }
        }

        // write this warp's 32x48 partial
        float* ps = psum + wid * (32 * PSR);
#pragma unroll
        for (int mt = 0; mt < 2; mt++) {
            int mr = mt * 16 + r_in;
#pragma unroll
            for (int nt = 0; nt < 6; nt++) {
                int n = nt * 8 + cc2;
                float* a = acc[mt * 6 + nt];
                *(float2*)(ps + mr * PSR + n)       = make_float2(a[0], a[1]);
                *(float2*)(ps + (mr + 8) * PSR + n) = make_float2(a[2], a[3]);
            }
        }
        __syncthreads();

        // epilogue: compute h(t+1), publish bf16 h first (cross-CTA data)
        __nv_bfloat16* hbn = g_hbf[(t + 1) & 1] + (size_t)b0 * Hn;
        float hnew2[2];
#pragma unroll
        for (int q = 0; q < 2; q++) {
            int i = ti[q], c = tc[q];
            float ghr = bhh_s[c], ghz = bhh_s[16 + c], ghn = bhh_s[32 + c];
#pragma unroll
            for (int w = 0; w < 8; w++) {
                const float* ps2 = psum + w * (32 * PSR) + i * PSR;
                ghr += ps2[c];
                ghz += ps2[16 + c];
                ghn += ps2[32 + c];
            }
            float r = sigfast(gxa[q][0] + ghr);
            float z = sigfast(gxa[q][1] + ghz);
            float n = tanhfast(gxa[q][2] + r * ghn);
            float hnew = (1.f - z) * n + z * hprev[q];
            hprev[q] = hnew;
            hnew2[q] = hnew;
            hbn[i * Hn + c0 + c] = __float2bfloat16(hnew);
        }

        if (t + 1 < Sn) {
            garrive(grp, idx);
#pragma unroll
            for (int q = 0; q < 2; q++)
                g_outs[(size_t)(b0 + ti[q]) * (Sn * Hn) + (size_t)t * Hn + c0 + tc[q]] = hnew2[q];
            const float* gxt = g_gx + (size_t)(t + 1) * (Bn * G3);
#pragma unroll
            for (int q = 0; q < 2; q++) {
                const float* gxr = gxt + (size_t)(b0 + ti[q]) * G3 + c0 + tc[q];
                gxa[q][0] = __ldg(gxr);
                gxa[q][1] = __ldg(gxr + 1024);
                gxa[q][2] = __ldg(gxr + 2048);
            }
            bt++;
            gwait(grp, base, bt);
        } else {
#pragma unroll
            for (int q = 0; q < 2; q++)
                g_outs[(size_t)(b0 + ti[q]) * (Sn * Hn) + (size_t)t * Hn + c0 + tc[q]] = hnew2[q];
        }
    }
}

// ---------------- k_logits ----------------
__global__ void __launch_bounds__(256) k_logits(const int* __restrict__ lab,
                                                const float* __restrict__ w_out,
                                                const float* __restrict__ b_out,
                                                float* __restrict__ out) {
    __shared__ float a_sm[16][68];
    __shared__ float b_sm[16][64];
    int m0 = blockIdx.x * 64;
    int tid = threadIdx.x;

    int ar = tid >> 2, akq = tid & 3;
    int bl = tid & 63, bkq = tid >> 6;
    const float* aptr = g_outs + (size_t)(m0 + ar) * Hn + akq * 4;
    int ty = tid >> 4, tx = tid & 15;

    float acc[4][4];
#pragma unroll
    for (int q = 0; q < 4; q++)
#pragma unroll
        for (int p = 0; p < 4; p++) acc[q][p] = 0.f;

    float4 av = *(const float4*)(aptr);
    float4 bv = make_float4(0.f, 0.f, 0.f, 0.f);
    if (bl < Ln) bv = *(const float4*)(w_out + (size_t)bl * Hn + bkq * 4);

    for (int k0 = 0; k0 < Hn; k0 += 16) {
        a_sm[akq * 4 + 0][ar] = av.x;
        a_sm[akq * 4 + 1][ar] = av.y;
        a_sm[akq * 4 + 2][ar] = av.z;
        a_sm[akq * 4 + 3][ar] = av.w;
        b_sm[bkq * 4 + 0][bl] = bv.x;
        b_sm[bkq * 4 + 1][bl] = bv.y;
        b_sm[bkq * 4 + 2][bl] = bv.z;
        b_sm[bkq * 4 + 3][bl] = bv.w;
        __syncthreads();
        if (k0 + 16 < Hn) {
            av = *(const float4*)(aptr + k0 + 16);
            if (bl < Ln) bv = *(const float4*)(w_out + (size_t)bl * Hn + bkq * 4 + k0 + 16);
        }
#pragma unroll
        for (int kk = 0; kk < 16; kk++) {
            float4 a4 = *(const float4*)&a_sm[kk][ty * 4];
            float4 b4 = *(const float4*)&b_sm[kk][tx * 4];
#pragma unroll
            for (int q = 0; q < 4; q++) {
                float aval = (q == 0) ? a4.x : (q == 1) ? a4.y : (q == 2) ? a4.z : a4.w;
                acc[q][0] = fmaf(aval, b4.x, acc[q][0]);
                acc[q][1] = fmaf(aval, b4.y, acc[q][1]);
                acc[q][2] = fmaf(aval, b4.z, acc[q][2]);
                acc[q][3] = fmaf(aval, b4.w, acc[q][3]);
            }
        }
        __syncthreads();
    }

#pragma unroll
    for (int q = 0; q < 4; q++) {
        int row = m0 + ty * 4 + q;
        int b = row >> 9, t = row & 511;
        int prev = (t == 0) ? 0 : clamp_lab(lab[b * Sn + t - 1]);
#pragma unroll
        for (int p = 0; p < 4; p++) {
            int l = tx * 4 + p;
            if (l < Ln) {
                float v = allowf(prev, l) ? (acc[q][p] + b_out[l]) : NEGV;
                out[(size_t)row * Ln + l] = v;
            }
        }
    }
}

// ---------------- launcher ----------------
extern "C" void kernel_launch(void* const* d_in, const int* in_sizes, int n_in,
                              void* d_out, int out_size) {
    const float* we    = nullptr;
    const int*   lab   = nullptr;
    const float* emb   = nullptr;
    const float* w_ih  = nullptr;
    const float* w_hh  = nullptr;
    const float* b_ih  = nullptr;
    const float* b_hh  = nullptr;
    const float* w_out = nullptr;
    const float* b_out = nullptr;

    for (int i = 0; i < n_in; i++) {
        int n = in_sizes[i];
        const void* p = d_in[i];
        switch (n) {
            case 33554432: we    = (const float*)p; break;
            case 32768:    lab   = (const int*)p;   break;
            case 6272:     emb   = (const float*)p; break;
            case 3538944:  w_ih  = (const float*)p; break;
            case 3145728:  w_hh  = (const float*)p; break;
            case 50176:    w_out = (const float*)p; break;
            case 49:       b_out = (const float*)p; break;
            case 3072:
                if (!b_ih) b_ih = (const float*)p; else b_hh = (const float*)p;
                break;
            default: break;
        }
    }
    float* out = (float*)d_out;

    cudaFuncSetAttribute(k_gx_mma,  cudaFuncAttributeMaxDynamicSharedMemorySize, GX_SMEM);
    cudaFuncSetAttribute(k_scan_tc, cudaFuncAttributeMaxDynamicSharedMemorySize, SCANTC_SMEM);

    k_lt      <<<dim3(24, Ln), 128>>>(emb, w_ih, b_ih);
    k_cast_a  <<<16384, 256>>>(we);
    k_cast_b  <<<1536, 256>>>(w_ih);
    k_gx_mma  <<<dim3(24, 256), 256, GX_SMEM>>>(lab);
    k_scan_tc <<<NCTA, TPB, SCANTC_SMEM>>>(w_hh, b_hh);
    k_logits  <<<Bn * Sn / 64, 256>>>(lab, w_out, b_out, out);
}

// round 15
// speedup vs baseline: 1.5792x; 1.1428x over previous
#include <cuda_runtime.h>
#include <cuda_bf16.h>
#include <math.h>

#define Bn 64
#define Sn 512
#define Hn 1024
#define En 128
#define Ln 49
#define G3 3072            // 3*H
#define IW 1152            // E+H
#define NEGV (-1e12f)

#define NCTA 128
#define TPB  256

// k_gx_mma: 128x128 CTA tile, 2-stage cp.async, 2 CTAs/SM (at HMMA ceiling)
#define GX_SMEM (2 * 2 * 128 * 64 * 2)   // 65536

// k_scan_tc smem: w 96KB + h 64KB + psum 8x32x50 fp32 50KB  (exact R12)
#define SCANTC_SMEM (98304 + 65536 + 51200)   // 215040

// k_logits_mma: A 128x64 bf16 (16KB) + B 64x64 bf16 (8KB), 2 stages
#define LG_SMEM (2 * (16384 + 8192))     // 49152

// ---------------- device scratch ----------------
__device__ __align__(16) float g_gx[(size_t)Bn * Sn * G3];     // [t][b][3H]
__device__ __align__(16) __nv_bfloat16 g_obf[(size_t)Bn * Sn * Hn];  // bf16 outs [b*512+t][1024]
__device__ __align__(16) float g_lt[Ln * G3];
__device__ __align__(16) __nv_bfloat16 g_hbf[2][Bn * Hn];      // bf16 h ping-pong
__device__ __align__(16) uint4 g_abf[(size_t)Bn * Sn * 128];   // bf16 A [m=t*64+b][1024]
__device__ __align__(16) uint4 g_bbf[(size_t)G3 * 128];        // bf16 B [g][1024]
__device__ __align__(16) __nv_bfloat16 g_wobf[64 * Hn];        // bf16 w_out padded to 64 rows
// per-group barrier state: counters and gen word on separate 128B lines
__device__ __align__(128) unsigned g_sub2[2][32];   // [grp][0..3]=sub counters, [grp][8]=root
__device__ __align__(128) unsigned g_gen3[2][32];   // [grp][0]=generation (monotonic)

// ---------------- PTX helpers ----------------
__device__ __forceinline__ unsigned smem_u32(const void* p) {
    unsigned a;
    asm("{ .reg .u64 t; cvta.to.shared.u64 t, %1; cvt.u32.u64 %0, t; }" : "=r"(a) : "l"(p));
    return a;
}
__device__ __forceinline__ void ldsm_x4(unsigned* r, unsigned addr) {
    asm volatile("ldmatrix.sync.aligned.m8n8.x4.shared.b16 {%0,%1,%2,%3}, [%4];"
                 : "=r"(r[0]), "=r"(r[1]), "=r"(r[2]), "=r"(r[3]) : "r"(addr));
}
__device__ __forceinline__ void ldsm_x2(unsigned* r, unsigned addr) {
    asm volatile("ldmatrix.sync.aligned.m8n8.x2.shared.b16 {%0,%1}, [%2];"
                 : "=r"(r[0]), "=r"(r[1]) : "r"(addr));
}
__device__ __forceinline__ void mma_bf16(float* c, const unsigned* a, const unsigned* b) {
    asm volatile(
        "mma.sync.aligned.m16n8k16.row.col.f32.bf16.bf16.f32 "
        "{%0,%1,%2,%3}, {%4,%5,%6,%7}, {%8,%9}, {%0,%1,%2,%3};"
        : "+f"(c[0]), "+f"(c[1]), "+f"(c[2]), "+f"(c[3])
        : "r"(a[0]), "r"(a[1]), "r"(a[2]), "r"(a[3]), "r"(b[0]), "r"(b[1]));
}
__device__ __forceinline__ float tanhfast(float x) {
    float y;
    asm("tanh.approx.f32 %0, %1;" : "=f"(y) : "f"(x));
    return y;
}
__device__ __forceinline__ float sigfast(float x) {
    return __fdividef(1.f, 1.f + __expf(-x));
}
#define CP_ASYNC16(sa, gp) \
    asm volatile("cp.async.cg.shared.global [%0], [%1], 16;" :: "r"(sa), "l"(gp) : "memory")
#define CP_COMMIT() asm volatile("cp.async.commit_group;" ::: "memory")
#define CP_WAITN(n) asm volatile("cp.async.wait_group %0;" :: "n"(n) : "memory")

// ---------------- split per-group barrier (arrive / per-warp wait) -------
__device__ __forceinline__ void garrive(int grp, int idx) {
    __threadfence();
    __syncthreads();
    if (threadIdx.x == 0) {
        if (atomicAdd(&g_sub2[grp][idx >> 4], 1u) == 15u) {
            atomicExch(&g_sub2[grp][idx >> 4], 0u);
            if (atomicAdd(&g_sub2[grp][8], 1u) == 3u) {
                atomicExch(&g_sub2[grp][8], 0u);
                __threadfence();
                atomicAdd(&g_gen3[grp][0], 1u);
            }
        }
    }
}
__device__ __forceinline__ void gwait(int grp, unsigned base, unsigned target) {
    if ((threadIdx.x & 31) == 0) {
        while ((unsigned)(*((volatile unsigned*)&g_gen3[grp][0]) - base) < target) {}
    }
    __syncwarp();
    __threadfence();
}

// ---------------- IOBES ----------------
__device__ __forceinline__ bool allowf(int prev, int nxt) {
    if (prev == 0 || ((prev - 1) & 3) >= 2) {
        if (nxt == 0) return true;
        int np = (nxt - 1) & 3;
        return (np == 0) || (np == 3);
    } else {
        if (nxt == 0) return false;
        int np = (nxt - 1) & 3;
        return (((nxt - 1) >> 2) == ((prev - 1) >> 2)) && (np == 1 || np == 2);
    }
}
__device__ __forceinline__ int clamp_lab(int v) {
    return v < 0 ? 0 : (v > Ln - 1 ? Ln - 1 : v);
}

// ---------------- k_lt ----------------
__global__ void k_lt(const float* __restrict__ emb,
                     const float* __restrict__ w_ih,
                     const float* __restrict__ b_ih) {
    int l = blockIdx.y;
    int g = blockIdx.x * 128 + threadIdx.x;
    __shared__ float es[En];
    if (threadIdx.x < En) es[threadIdx.x] = emb[l * En + threadIdx.x];
    __syncthreads();
    float acc = b_ih[g];
    const float* w = w_ih + (size_t)g * IW;
#pragma unroll 8
    for (int e = 0; e < En; e++) acc = fmaf(es[e], w[e], acc);
    g_lt[l * G3 + g] = acc;
}

// ---------------- bf16 cast kernels ----------------
__device__ __forceinline__ unsigned pk2(float a, float b) {
    __nv_bfloat162 h = __floats2bfloat162_rn(a, b);
    return *(unsigned*)&h;
}
__global__ void k_cast_a(const float* __restrict__ we) {
    size_t c = (size_t)blockIdx.x * 256 + threadIdx.x;
    int m = (int)(c >> 7), kq = (int)(c & 127);
    int t = m >> 6, b = m & 63;
    const float4* src = (const float4*)(we + ((size_t)b * Sn + t) * Hn + kq * 8);
    float4 f0 = src[0], f1 = src[1];
    uint4 o;
    o.x = pk2(f0.x, f0.y); o.y = pk2(f0.z, f0.w);
    o.z = pk2(f1.x, f1.y); o.w = pk2(f1.z, f1.w);
    g_abf[c] = o;
}
__global__ void k_cast_b(const float* __restrict__ w_ih) {
    size_t c = (size_t)blockIdx.x * 256 + threadIdx.x;
    int g = (int)(c >> 7), kq = (int)(c & 127);
    const float4* src = (const float4*)(w_ih + (size_t)g * IW + En + kq * 8);
    float4 f0 = src[0], f1 = src[1];
    uint4 o;
    o.x = pk2(f0.x, f0.y); o.y = pk2(f0.z, f0.w);
    o.z = pk2(f1.x, f1.y); o.w = pk2(f1.z, f1.w);
    g_bbf[c] = o;
}
// w_out -> bf16 padded to 64 rows (rows 49..63 zero)
__global__ void k_cast_wo(const float* __restrict__ w_out) {
    int idx = blockIdx.x * 256 + threadIdx.x;   // 0..8191 (uint = 2 bf16)
    int r = idx >> 9, cp = idx & 511;           // 64 rows x 512 pairs
    unsigned v = 0u;
    if (r < Ln) v = pk2(w_out[r * Hn + cp * 2], w_out[r * Hn + cp * 2 + 1]);
    ((unsigned*)g_wobf)[idx] = v;
}

// ---------------- k_gx_mma: HMMA bf16 GEMM, 2-stage cp.async (ceiling) ----
__global__ void __launch_bounds__(256, 2) k_gx_mma(const int* __restrict__ lab) {
    extern __shared__ char smem[];
    unsigned sb = smem_u32(smem);
    const unsigned aOff[2] = { 0u, 32768u };
    const unsigned bOff[2] = { 16384u, 49152u };

    int tid = threadIdx.x, lane = tid & 31, wid = tid >> 5;
    int wm = wid >> 2, wn = wid & 3;
    int n0 = blockIdx.x * 128;
    int m0 = blockIdx.y * 128;

    float acc[16][4];
#pragma unroll
    for (int i = 0; i < 16; i++)
#pragma unroll
        for (int j = 0; j < 4; j++) acc[i][j] = 0.f;

#pragma unroll
    for (int q = 0; q < 4; q++) {
        int idx = tid * 4 + q, r = idx >> 3, i = idx & 7;
        unsigned off = (unsigned)(r * 128 + ((i ^ (r & 7)) << 4));
        CP_ASYNC16(sb + aOff[0] + off, g_abf + (size_t)(m0 + r) * 128 + i);
        CP_ASYNC16(sb + bOff[0] + off, g_bbf + (size_t)(n0 + r) * 128 + i);
    }
    CP_COMMIT();

    int il = lane & 15;
    for (int kc = 0; kc < 16; kc++) {
        int s = kc & 1;
        if (kc < 15) {
            int kn = kc + 1, sn = kn & 1;
#pragma unroll
            for (int q = 0; q < 4; q++) {
                int idx = tid * 4 + q, r = idx >> 3, i = idx & 7;
                unsigned off = (unsigned)(r * 128 + ((i ^ (r & 7)) << 4));
                CP_ASYNC16(sb + aOff[sn] + off, g_abf + (size_t)(m0 + r) * 128 + kn * 8 + i);
                CP_ASYNC16(sb + bOff[sn] + off, g_bbf + (size_t)(n0 + r) * 128 + kn * 8 + i);
            }
            CP_COMMIT();
            CP_WAITN(1);
        } else {
            CP_WAITN(0);
        }
        __syncthreads();
#pragma unroll
        for (int ks = 0; ks < 4; ks++) {
            unsigned afr[4][4], bfr[4][2];
#pragma unroll
            for (int mt = 0; mt < 4; mt++) {
                int row = wm * 64 + mt * 16 + il;
                int ch = ks * 2 + (lane >> 4);
                ldsm_x4(afr[mt], sb + aOff[s] + row * 128 + ((ch ^ (row & 7)) << 4));
            }
#pragma unroll
            for (int nt = 0; nt < 4; nt++) {
                int row = wn * 32 + nt * 8 + (il & 7);
                int ch = ks * 2 + (il >> 3);
                ldsm_x2(bfr[nt], sb + bOff[s] + row * 128 + ((ch ^ (row & 7)) << 4));
            }
#pragma unroll
            for (int mt = 0; mt < 4; mt++)
#pragma unroll
                for (int nt = 0; nt < 4; nt++)
                    mma_bf16(acc[mt * 4 + nt], afr[mt], bfr[nt]);
        }
        __syncthreads();
    }

    int r_in = lane >> 2, c2 = (lane & 3) * 2;
#pragma unroll
    for (int mt = 0; mt < 4; mt++) {
        int r0 = m0 + wm * 64 + mt * 16 + r_in;
        int r1 = r0 + 8;
        int t0 = r0 >> 6, bb0 = r0 & 63;
        int t1 = r1 >> 6, bb1 = r1 & 63;
        int p0 = (t0 == 0) ? 0 : clamp_lab(lab[bb0 * Sn + t0 - 1]);
        int p1 = (t1 == 0) ? 0 : clamp_lab(lab[bb1 * Sn + t1 - 1]);
        const float* lt0 = g_lt + (size_t)p0 * G3;
        const float* lt1 = g_lt + (size_t)p1 * G3;
        float* o0 = g_gx + (size_t)r0 * G3;
        float* o1 = g_gx + (size_t)r1 * G3;
#pragma unroll
        for (int nt = 0; nt < 4; nt++) {
            int n = n0 + wn * 32 + nt * 8 + c2;
            float* a = acc[mt * 4 + nt];
            float2 v0, v1;
            v0.x = a[0] + lt0[n]; v0.y = a[1] + lt0[n + 1];
            v1.x = a[2] + lt1[n]; v1.y = a[3] + lt1[n + 1];
            *(float2*)(o0 + n) = v0;
            *(float2*)(o1 + n) = v1;
        }
    }
}

// ---------------- k_scan_tc: batch-split persistent GRU scan (exact R12) --
// Only change vs R12: h output stored as bf16 to g_obf (consumed by
// k_logits_mma) instead of fp32 g_outs.
#define PSR 50      // psum row stride (floats)
__global__ void __launch_bounds__(TPB, 1) k_scan_tc(const float* __restrict__ w_hh,
                                                    const float* __restrict__ b_hh) {
    extern __shared__ char smem[];
    unsigned sb = smem_u32(smem);
    char* w_sm = smem;                        // bf16 [8 kc][48 j][256B], swizzled
    float* psum = (float*)(smem + 98304 + 65536);  // [8 w][32][PSR]
    __shared__ float bhh_s[48];
    __shared__ unsigned s_base;
    const unsigned swb = sb;
    const unsigned sh0 = sb + 98304;          // h: [8 kc][32 r][256B], swizzled

    int cta = blockIdx.x, tid = threadIdx.x;
    int lane = tid & 31, wid = tid >> 5;
    int grp = cta >> 6, idx = cta & 63;
    int c0 = idx * 16;
    int b0 = grp * 32;

    if (tid == 0) s_base = *((volatile unsigned*)&g_gen3[grp][0]);

    // one-time: weights (48 rows x 1024) -> bf16 smem (ldmatrix layout)
    for (int cid = tid; cid < 6144; cid += TPB) {
        int j = cid >> 7, kchunk = cid & 127;
        int kc = kchunk >> 4, c16 = kchunk & 15;
        int wrow = (j >> 4) * Hn + c0 + (j & 15);
        const float4* s = (const float4*)(w_hh + (size_t)wrow * Hn + kchunk * 8);
        float4 f0 = s[0], f1 = s[1];
        uint4 o;
        o.x = pk2(f0.x, f0.y); o.y = pk2(f0.z, f0.w);
        o.z = pk2(f1.x, f1.y); o.w = pk2(f1.z, f1.w);
        *(uint4*)(w_sm + kc * 12288 + j * 256 + ((c16 ^ (j & 7)) << 4)) = o;
    }
    if (tid < 48) bhh_s[tid] = b_hh[(tid >> 4) * Hn + c0 + (tid & 15)];

    // zero this group's h rows in buffer 0
    for (int i2 = idx * TPB + tid; i2 < 32 * Hn * 2 / 16; i2 += 64 * TPB)
        ((uint4*)(g_hbf[0] + (size_t)b0 * Hn))[i2] = make_uint4(0u, 0u, 0u, 0u);

    garrive(grp, idx);
    unsigned base = s_base;
    unsigned bt = 1;
    gwait(grp, base, bt);

    int il = lane & 15;
    int r_in = lane >> 2, cc2 = (lane & 3) * 2;
    int kk = wid;                       // this warp's k16 slot (0..7)

    // epilogue task mapping: 32 batches x 16 cols = 512 tasks, 2/thread
    int ti[2], tc[2];
    ti[0] = tid >> 4;           tc[0] = tid & 15;
    ti[1] = (tid + TPB) >> 4;   tc[1] = tid & 15;
    float hprev[2] = { 0.f, 0.f };

    // prefetch gx for t=0
    float gxa[2][3];
#pragma unroll
    for (int q = 0; q < 2; q++) {
        const float* gxr = g_gx + (size_t)(b0 + ti[q]) * G3 + c0 + tc[q];
        gxa[q][0] = __ldg(gxr);
        gxa[q][1] = __ldg(gxr + 1024);
        gxa[q][2] = __ldg(gxr + 2048);
    }

    for (int t = 0; t < Sn; t++) {
        const __nv_bfloat16* hb = g_hbf[t & 1] + (size_t)b0 * Hn;

        // issue ALL 4 chunk-pairs of h(t) as separate commit groups (coalesced)
#pragma unroll
        for (int kcp = 0; kcp < 4; kcp++) {
#pragma unroll
            for (int q = 0; q < 4; q++) {
                int i2 = q * 256 + tid;          // 0..1023 within pair
                int r = i2 >> 5, u = i2 & 31;
                int kc = kcp * 2 + (u >> 4), c16 = u & 15;
                unsigned dst = sh0 + kc * 8192 + r * 256 + ((c16 ^ (r & 7)) << 4);
                CP_ASYNC16(dst, hb + (size_t)r * Hn + kc * 128 + c16 * 8);
            }
            CP_COMMIT();
        }

        float acc[12][4];
#pragma unroll
        for (int i = 0; i < 12; i++)
#pragma unroll
            for (int j = 0; j < 4; j++) acc[i][j] = 0.f;

#pragma unroll
        for (int kcp = 0; kcp < 4; kcp++) {
            if (kcp == 0)      CP_WAITN(3);
            else if (kcp == 1) CP_WAITN(2);
            else if (kcp == 2) CP_WAITN(1);
            else               CP_WAITN(0);
            __syncthreads();
#pragma unroll
            for (int sub = 0; sub < 2; sub++) {
                int kc = kcp * 2 + sub;
                unsigned a[2][4];
#pragma unroll
                for (int mt = 0; mt < 2; mt++) {
                    int row = mt * 16 + il;
                    int ch = kk * 2 + (lane >> 4);
                    ldsm_x4(a[mt], sh0 + kc * 8192 + row * 256 + ((ch ^ (row & 7)) << 4));
                }
                unsigned bfr[6][2];
#pragma unroll
                for (int nt = 0; nt < 6; nt++) {
                    int row = nt * 8 + (il & 7);
                    int ch = kk * 2 + (il >> 3);
                    ldsm_x2(bfr[nt], swb + kc * 12288 + row * 256 + ((ch ^ (row & 7)) << 4));
                }
#pragma unroll
                for (int mt = 0; mt < 2; mt++)
#pragma unroll
                    for (int nt = 0; nt < 6; nt++)
                        mma_bf16(acc[mt * 6 + nt], a[mt], bfr[nt]);
            }
        }

        // write this warp's 32x48 partial
        float* ps = psum + wid * (32 * PSR);
#pragma unroll
        for (int mt = 0; mt < 2; mt++) {
            int mr = mt * 16 + r_in;
#pragma unroll
            for (int nt = 0; nt < 6; nt++) {
                int n = nt * 8 + cc2;
                float* a = acc[mt * 6 + nt];
                *(float2*)(ps + mr * PSR + n)       = make_float2(a[0], a[1]);
                *(float2*)(ps + (mr + 8) * PSR + n) = make_float2(a[2], a[3]);
            }
        }
        __syncthreads();

        // epilogue: compute h(t+1), publish bf16 h first (cross-CTA data)
        __nv_bfloat16* hbn = g_hbf[(t + 1) & 1] + (size_t)b0 * Hn;
        float hnew2[2];
#pragma unroll
        for (int q = 0; q < 2; q++) {
            int i = ti[q], c = tc[q];
            float ghr = bhh_s[c], ghz = bhh_s[16 + c], ghn = bhh_s[32 + c];
#pragma unroll
            for (int w = 0; w < 8; w++) {
                const float* ps2 = psum + w * (32 * PSR) + i * PSR;
                ghr += ps2[c];
                ghz += ps2[16 + c];
                ghn += ps2[32 + c];
            }
            float r = sigfast(gxa[q][0] + ghr);
            float z = sigfast(gxa[q][1] + ghz);
            float n = tanhfast(gxa[q][2] + r * ghn);
            float hnew = (1.f - z) * n + z * hprev[q];
            hprev[q] = hnew;
            hnew2[q] = hnew;
            hbn[i * Hn + c0 + c] = __float2bfloat16(hnew);
        }

        if (t + 1 < Sn) {
            garrive(grp, idx);
#pragma unroll
            for (int q = 0; q < 2; q++)
                g_obf[((size_t)(b0 + ti[q]) * Sn + t) * Hn + c0 + tc[q]] =
                    __float2bfloat16(hnew2[q]);
            const float* gxt = g_gx + (size_t)(t + 1) * (Bn * G3);
#pragma unroll
            for (int q = 0; q < 2; q++) {
                const float* gxr = gxt + (size_t)(b0 + ti[q]) * G3 + c0 + tc[q];
                gxa[q][0] = __ldg(gxr);
                gxa[q][1] = __ldg(gxr + 1024);
                gxa[q][2] = __ldg(gxr + 2048);
            }
            bt++;
            gwait(grp, base, bt);
        } else {
#pragma unroll
            for (int q = 0; q < 2; q++)
                g_obf[((size_t)(b0 + ti[q]) * Sn + t) * Hn + c0 + tc[q]] =
                    __float2bfloat16(hnew2[q]);
        }
    }
}

// ---------------- k_logits_mma: HMMA logits + IOBES mask ------------------
// rows m = b*512+t (g_obf layout); CTA tile 128 x 64 (49 valid cols), K=1024.
// 8 warps: warp w owns rows [w*16, w*16+16), all 64 cols.
__global__ void __launch_bounds__(256, 2) k_logits_mma(const int* __restrict__ lab,
                                                       const float* __restrict__ b_out,
                                                       float* __restrict__ out) {
    extern __shared__ char smem[];
    unsigned sb = smem_u32(smem);
    const unsigned aOff[2] = { 0u, 24576u };
    const unsigned bOff[2] = { 16384u, 40960u };

    int tid = threadIdx.x, lane = tid & 31, wid = tid >> 5;
    int m0 = blockIdx.x * 128;

    float acc[8][4];
#pragma unroll
    for (int i = 0; i < 8; i++)
#pragma unroll
        for (int j = 0; j < 4; j++) acc[i][j] = 0.f;

    // issue stage 0: A 128x64 bf16 (1024 chunks, 4/thread), B 64x64 (512, 2/thread)
#pragma unroll
    for (int q = 0; q < 4; q++) {
        int idx = tid * 4 + q, r = idx >> 3, i = idx & 7;
        unsigned off = (unsigned)(r * 128 + ((i ^ (r & 7)) << 4));
        CP_ASYNC16(sb + aOff[0] + off, g_obf + (size_t)(m0 + r) * Hn + i * 8);
    }
#pragma unroll
    for (int q = 0; q < 2; q++) {
        int idx = tid * 2 + q, r = idx >> 3, i = idx & 7;
        unsigned off = (unsigned)(r * 128 + ((i ^ (r & 7)) << 4));
        CP_ASYNC16(sb + bOff[0] + off, g_wobf + (size_t)r * Hn + i * 8);
    }
    CP_COMMIT();

    int il = lane & 15;
    for (int kc = 0; kc < 16; kc++) {
        int s = kc & 1;
        if (kc < 15) {
            int kn = kc + 1, sn = kn & 1;
#pragma unroll
            for (int q = 0; q < 4; q++) {
                int idx = tid * 4 + q, r = idx >> 3, i = idx & 7;
                unsigned off = (unsigned)(r * 128 + ((i ^ (r & 7)) << 4));
                CP_ASYNC16(sb + aOff[sn] + off, g_obf + (size_t)(m0 + r) * Hn + kn * 64 + i * 8);
            }
#pragma unroll
            for (int q = 0; q < 2; q++) {
                int idx = tid * 2 + q, r = idx >> 3, i = idx & 7;
                unsigned off = (unsigned)(r * 128 + ((i ^ (r & 7)) << 4));
                CP_ASYNC16(sb + bOff[sn] + off, g_wobf + (size_t)r * Hn + kn * 64 + i * 8);
            }
            CP_COMMIT();
            CP_WAITN(1);
        } else {
            CP_WAITN(0);
        }
        __syncthreads();
#pragma unroll
        for (int ks = 0; ks < 4; ks++) {
            unsigned afr[4], bfr[8][2];
            {
                int row = wid * 16 + il;
                int ch = ks * 2 + (lane >> 4);
                ldsm_x4(afr, sb + aOff[s] + row * 128 + ((ch ^ (row & 7)) << 4));
            }
#pragma unroll
            for (int nt = 0; nt < 8; nt++) {
                int row = nt * 8 + (il & 7);
                int ch = ks * 2 + (il >> 3);
                ldsm_x2(bfr[nt], sb + bOff[s] + row * 128 + ((ch ^ (row & 7)) << 4));
            }
#pragma unroll
            for (int nt = 0; nt < 8; nt++)
                mma_bf16(acc[nt], afr, bfr[nt]);
        }
        __syncthreads();
    }

    // epilogue: bias + IOBES mask, write [row][49]
    int r_in = lane >> 2, c2 = (lane & 3) * 2;
    int r0 = m0 + wid * 16 + r_in;
    int r1 = r0 + 8;
    int bb0 = r0 >> 9, t0 = r0 & 511;
    int bb1 = r1 >> 9, t1 = r1 & 511;
    int p0 = (t0 == 0) ? 0 : clamp_lab(lab[bb0 * Sn + t0 - 1]);
    int p1 = (t1 == 0) ? 0 : clamp_lab(lab[bb1 * Sn + t1 - 1]);
    float* o0 = out + (size_t)r0 * Ln;
    float* o1 = out + (size_t)r1 * Ln;
#pragma unroll
    for (int nt = 0; nt < 8; nt++) {
        int l = nt * 8 + c2;
        float* a = acc[nt];
        if (l < Ln) {
            float bo = __ldg(b_out + l);
            o0[l] = allowf(p0, l) ? (a[0] + bo) : NEGV;
            o1[l] = allowf(p1, l) ? (a[2] + bo) : NEGV;
        }
        if (l + 1 < Ln) {
            float bo = __ldg(b_out + l + 1);
            o0[l + 1] = allowf(p0, l + 1) ? (a[1] + bo) : NEGV;
            o1[l + 1] = allowf(p1, l + 1) ? (a[3] + bo) : NEGV;
        }
    }
}

// ---------------- launcher ----------------
extern "C" void kernel_launch(void* const* d_in, const int* in_sizes, int n_in,
                              void* d_out, int out_size) {
    const float* we    = nullptr;
    const int*   lab   = nullptr;
    const float* emb   = nullptr;
    const float* w_ih  = nullptr;
    const float* w_hh  = nullptr;
    const float* b_ih  = nullptr;
    const float* b_hh  = nullptr;
    const float* w_out = nullptr;
    const float* b_out = nullptr;

    for (int i = 0; i < n_in; i++) {
        int n = in_sizes[i];
        const void* p = d_in[i];
        switch (n) {
            case 33554432: we    = (const float*)p; break;
            case 32768:    lab   = (const int*)p;   break;
            case 6272:     emb   = (const float*)p; break;
            case 3538944:  w_ih  = (const float*)p; break;
            case 3145728:  w_hh  = (const float*)p; break;
            case 50176:    w_out = (const float*)p; break;
            case 49:       b_out = (const float*)p; break;
            case 3072:
                if (!b_ih) b_ih = (const float*)p; else b_hh = (const float*)p;
                break;
            default: break;
        }
    }
    float* out = (float*)d_out;

    cudaFuncSetAttribute(k_gx_mma,     cudaFuncAttributeMaxDynamicSharedMemorySize, GX_SMEM);
    cudaFuncSetAttribute(k_scan_tc,    cudaFuncAttributeMaxDynamicSharedMemorySize, SCANTC_SMEM);
    cudaFuncSetAttribute(k_logits_mma, cudaFuncAttributeMaxDynamicSharedMemorySize, LG_SMEM);

    k_lt         <<<dim3(24, Ln), 128>>>(emb, w_ih, b_ih);
    k_cast_a     <<<16384, 256>>>(we);
    k_cast_b     <<<1536, 256>>>(w_ih);
    k_cast_wo    <<<128, 256>>>(w_out);
    k_gx_mma     <<<dim3(24, 256), 256, GX_SMEM>>>(lab);
    k_scan_tc    <<<NCTA, TPB, SCANTC_SMEM>>>(w_hh, b_hh);
    k_logits_mma <<<Bn * Sn / 128, 256, LG_SMEM>>>(lab, b_out, out);
}